// round 1
// baseline (speedup 1.0000x reference)
#include <cuda_runtime.h>
#include <math.h>
#include <stdint.h>

#define NB 2
#define MM 512
#define DD 128
#define HH 8
#define DIN 64
#define NM (NB*MM)   // 1024

// ---------------- scratch (device globals; no allocation allowed) ----------------
#define OFF_TMP  0                               // [NM, 2D]  f_node hidden
#define OFF_H    (OFF_TMP + NM*2*DD)             // [NM, D]   h
#define OFF_K    (OFF_H   + NM*DD)               // [H, NM, D]
#define OFF_Q    (OFF_K   + HH*NM*DD)
#define OFF_V    (OFF_Q   + HH*NM*DD)
#define OFF_S    (OFF_V   + HH*NM*DD)            // [H*N, M, M] scores/alpha
#define OFF_ATT  (OFF_S   + HH*NB*MM*MM)         // [H, NM, D]
#define OFF_ATTC (OFF_ATT + HH*NM*DD)            // [NM, H*D] head-concat
#define OFF_T2   (OFF_ATTC+ HH*NM*DD)            // [NM, D]   f_v hidden
#define OFF_AB   (OFF_T2  + NM*DD)               // [2, NM, D] A/B for edges
#define SCRATCH_TOTAL (OFF_AB + 2*NM*DD)

__device__ float g_scratch[SCRATCH_TOTAL];

enum { F_TRANSB=1, F_RELU=2, F_LEAKY=4, F_TE=8, F_BIAS=16, F_ADD=32 };

// ---------------- generic batched fp32 GEMM: C = act(A @ B(^T) + bias) (+ add) ---
// block 256 threads, 64x64 output tile, K-tile 16, 4x4 per thread.
// A: [Mr,Kd] row-major. B: [Kd,Nc] (or [Nc,Kd] if TRANSB). C: [Mr,Nc].
// All dims multiples of tile sizes (guaranteed by problem shapes).
__global__ __launch_bounds__(256)
void gemm_k(const float* __restrict__ A, const float* __restrict__ B,
            const float* __restrict__ bias, const float* __restrict__ addsrc,
            float* __restrict__ C,
            int Mr, int Nc, int Kd,
            int64_t sA, int64_t sB, int64_t sBias, int64_t sC,
            int flags)
{
    __shared__ float As[16][68];
    __shared__ float Bs[16][68];
    int z = blockIdx.z;
    A += sA * z; B += sB * z; C += sC * z;
    if (flags & F_BIAS) bias += sBias * z;

    int tid = threadIdx.x;
    int tx = tid & 15, ty = tid >> 4;
    int m0 = blockIdx.y << 6, n0 = blockIdx.x << 6;
    float acc[4][4] = {};
    int ldb = (flags & F_TRANSB) ? Kd : Nc;

    for (int k0 = 0; k0 < Kd; k0 += 16) {
        // ---- load A tile (64 x 16), store transposed As[k][m]
        {
            int r = tid >> 2, c = (tid & 3) << 2;
            float4 a4 = *(const float4*)(A + (int64_t)(m0 + r) * Kd + k0 + c);
            if (flags & F_TE) {
                a4.x += sinf((float)(k0 + c + 0) * (5.0f / 63.0f));
                a4.y += sinf((float)(k0 + c + 1) * (5.0f / 63.0f));
                a4.z += sinf((float)(k0 + c + 2) * (5.0f / 63.0f));
                a4.w += sinf((float)(k0 + c + 3) * (5.0f / 63.0f));
            }
            As[c + 0][r] = a4.x; As[c + 1][r] = a4.y;
            As[c + 2][r] = a4.z; As[c + 3][r] = a4.w;
        }
        // ---- load B tile into Bs[k][n]
        if (flags & F_TRANSB) {
            int j = tid >> 2, c = (tid & 3) << 2;
            float4 b4 = *(const float4*)(B + (int64_t)(n0 + j) * ldb + k0 + c);
            Bs[c + 0][j] = b4.x; Bs[c + 1][j] = b4.y;
            Bs[c + 2][j] = b4.z; Bs[c + 3][j] = b4.w;
        } else {
            int kk = tid >> 4, c = (tid & 15) << 2;
            float4 b4 = *(const float4*)(B + (int64_t)(k0 + kk) * ldb + n0 + c);
            *(float4*)&Bs[kk][c] = b4;
        }
        __syncthreads();
        #pragma unroll
        for (int kk = 0; kk < 16; kk++) {
            float4 av = *(const float4*)&As[kk][ty << 2];
            float4 bv = *(const float4*)&Bs[kk][tx << 2];
            float a[4] = {av.x, av.y, av.z, av.w};
            float b[4] = {bv.x, bv.y, bv.z, bv.w};
            #pragma unroll
            for (int i = 0; i < 4; i++)
                #pragma unroll
                for (int j = 0; j < 4; j++)
                    acc[i][j] = fmaf(a[i], b[j], acc[i][j]);
        }
        __syncthreads();
    }

    #pragma unroll
    for (int i = 0; i < 4; i++) {
        int row = m0 + (ty << 2) + i;
        #pragma unroll
        for (int j = 0; j < 4; j++) {
            int col = n0 + (tx << 2) + j;
            float v = acc[i][j];
            if (flags & F_BIAS)  v += bias[col];
            if (flags & F_RELU)  v = fmaxf(v, 0.0f);
            if (flags & F_LEAKY) v = (v >= 0.0f) ? v : 0.2f * v;
            if (flags & F_ADD)   v += addsrc[(int64_t)row * Nc + col];
            C[(int64_t)row * Nc + col] = v;
        }
    }
}

// ---------------- row softmax over 512 cols (one block per row) -------------------
__global__ __launch_bounds__(256)
void softmax_k(float* __restrict__ data)
{
    __shared__ float red[8];
    float* p = data + (int64_t)blockIdx.x * MM;
    int t = threadIdx.x;
    float v0 = p[t], v1 = p[t + 256];
    float m = fmaxf(v0, v1);
    #pragma unroll
    for (int o = 16; o; o >>= 1) m = fmaxf(m, __shfl_xor_sync(0xffffffffu, m, o));
    if ((t & 31) == 0) red[t >> 5] = m;
    __syncthreads();
    float bm = red[0];
    #pragma unroll
    for (int w = 1; w < 8; w++) bm = fmaxf(bm, red[w]);
    float e0 = __expf(v0 - bm), e1 = __expf(v1 - bm);
    float s = e0 + e1;
    #pragma unroll
    for (int o = 16; o; o >>= 1) s += __shfl_xor_sync(0xffffffffu, s, o);
    __syncthreads();
    if ((t & 31) == 0) red[t >> 5] = s;
    __syncthreads();
    float bs = red[0];
    #pragma unroll
    for (int w = 1; w < 8; w++) bs += red[w];
    float inv = 1.0f / bs;
    p[t] = e0 * inv;
    p[t + 256] = e1 * inv;
}

// ---------------- [H][N*M][D] -> [N*M][H*D] head-concat reorder -------------------
__global__ __launch_bounds__(256)
void reorder_k(const float4* __restrict__ in, float4* __restrict__ out)
{
    int idx = blockIdx.x * 256 + threadIdx.x;   // 0 .. 262143 (float4 units)
    int d4 = idx & 31;
    int h  = (idx >> 5) & 7;
    int m  = (idx >> 8) & 511;
    int n  = idx >> 17;
    out[(int64_t)(n * 512 + m) * 256 + h * 32 + d4] =
        in[((int64_t)(h * 2 + n) * 512 + m) * 32 + d4];
}

// ---------------- edge kernel: edge[n,i,j] = (sum_d relu(A_i+B_j+b1)*w2 + b2)/M ---
// 32x32 (i,j) tile per block; A/B tiles staged transposed in smem (b1 folded in).
__global__ __launch_bounds__(256)
void edge_k(const float* __restrict__ AB, const float* __restrict__ b1,
            const float* __restrict__ w2, const float* __restrict__ b2,
            float* __restrict__ out)
{
    __shared__ float Ast[DD][36];
    __shared__ float Bst[DD][36];
    __shared__ float w2s[DD];
    int n  = blockIdx.z;
    int i0 = blockIdx.y << 5, j0 = blockIdx.x << 5;
    const float* Ab = AB + ((int64_t)n * MM + i0) * DD;
    const float* Bb = AB + (int64_t)NM * DD + ((int64_t)n * MM + j0) * DD;
    int t = threadIdx.x;
    if (t < DD) w2s[t] = w2[t];
    #pragma unroll
    for (int c = 0; c < 4; c++) {
        int idx = t + (c << 8);        // 0..1023 float4 slots (32 rows x 32 f4)
        int r  = idx >> 5;             // 0..31
        int d4 = (idx & 31) << 2;      // 0..124
        float4 a = *(const float4*)(Ab + r * DD + d4);
        Ast[d4 + 0][r] = a.x; Ast[d4 + 1][r] = a.y;
        Ast[d4 + 2][r] = a.z; Ast[d4 + 3][r] = a.w;
        float4 bvl = *(const float4*)(Bb + r * DD + d4);
        float4 bb  = *(const float4*)(b1 + d4);
        Bst[d4 + 0][r] = bvl.x + bb.x; Bst[d4 + 1][r] = bvl.y + bb.y;
        Bst[d4 + 2][r] = bvl.z + bb.z; Bst[d4 + 3][r] = bvl.w + bb.w;
    }
    __syncthreads();
    int tx = t & 15, ty = t >> 4;      // each thread: 2x2 outputs
    float a00 = 0.f, a01 = 0.f, a10 = 0.f, a11 = 0.f;
    #pragma unroll 8
    for (int d = 0; d < DD; d++) {
        float2 av = *(const float2*)&Ast[d][ty << 1];
        float2 bv = *(const float2*)&Bst[d][tx << 1];
        float w = w2s[d];
        a00 = fmaf(fmaxf(av.x + bv.x, 0.f), w, a00);
        a01 = fmaf(fmaxf(av.x + bv.y, 0.f), w, a01);
        a10 = fmaf(fmaxf(av.y + bv.x, 0.f), w, a10);
        a11 = fmaf(fmaxf(av.y + bv.y, 0.f), w, a11);
    }
    float bb = b2[0];
    const float sc = 1.0f / (float)MM;
    int i = i0 + (ty << 1), j = j0 + (tx << 1);
    float* o = out + ((int64_t)n * MM + i) * MM + j;
    o[0]      = (a00 + bb) * sc;
    o[1]      = (a01 + bb) * sc;
    o[MM]     = (a10 + bb) * sc;
    o[MM + 1] = (a11 + bb) * sc;
}

// ---------------- host launcher ---------------------------------------------------
extern "C" void kernel_launch(void* const* d_in, const int* in_sizes, int n_in,
                              void* d_out, int out_size)
{
    const float* x     = (const float*)d_in[0];
    const float* fn_w1 = (const float*)d_in[1];
    const float* fn_b1 = (const float*)d_in[2];
    const float* fn_w2 = (const float*)d_in[3];
    const float* fn_b2 = (const float*)d_in[4];
    const float* wk    = (const float*)d_in[5];
    const float* bk    = (const float*)d_in[6];
    const float* wq    = (const float*)d_in[7];
    const float* bq    = (const float*)d_in[8];
    const float* wv    = (const float*)d_in[9];
    const float* bv    = (const float*)d_in[10];
    const float* fv_w1 = (const float*)d_in[11];
    const float* fv_b1 = (const float*)d_in[12];
    const float* fv_w2 = (const float*)d_in[13];
    const float* fv_b2 = (const float*)d_in[14];
    const float* fe_w1 = (const float*)d_in[15];
    const float* fe_b1 = (const float*)d_in[16];
    const float* fe_w2 = (const float*)d_in[17];
    const float* fe_b2 = (const float*)d_in[18];

    float* scratch = nullptr;
    cudaGetSymbolAddress((void**)&scratch, g_scratch);
    float* tmp  = scratch + OFF_TMP;
    float* h    = scratch + OFF_H;
    float* K    = scratch + OFF_K;
    float* Q    = scratch + OFF_Q;
    float* V    = scratch + OFF_V;
    float* S    = scratch + OFF_S;
    float* att  = scratch + OFF_ATT;
    float* attc = scratch + OFF_ATTC;
    float* t2   = scratch + OFF_T2;
    float* ABuf = scratch + OFF_AB;

    float* x2   = (float*)d_out;              // [N,M,D]
    float* edge = (float*)d_out + NM * DD;    // [N,M,M]

    dim3 blk(256);

    // 1) f_node hidden: relu((x+te) @ fn_w1 + fn_b1)   [1024,64]@[64,256]
    gemm_k<<<dim3(4, 16, 1), blk>>>(x, fn_w1, fn_b1, nullptr, tmp,
                                    NM, 2 * DD, DIN, 0, 0, 0, 0,
                                    F_TE | F_RELU | F_BIAS);
    // 2) h = tmp @ fn_w2 + fn_b2                        [1024,256]@[256,128]
    gemm_k<<<dim3(2, 16, 1), blk>>>(tmp, fn_w2, fn_b2, nullptr, h,
                                    NM, DD, 2 * DD, 0, 0, 0, 0, F_BIAS);
    // 3) K/Q/V: batched over 8 heads                    [1024,128]@[128,128]
    gemm_k<<<dim3(2, 16, HH), blk>>>(h, wk, bk, nullptr, K,
                                     NM, DD, DD, 0, DD * DD, DD, NM * DD, F_BIAS);
    gemm_k<<<dim3(2, 16, HH), blk>>>(h, wq, bq, nullptr, Q,
                                     NM, DD, DD, 0, DD * DD, DD, NM * DD, F_BIAS);
    gemm_k<<<dim3(2, 16, HH), blk>>>(h, wv, bv, nullptr, V,
                                     NM, DD, DD, 0, DD * DD, DD, NM * DD, F_BIAS);
    // 4) scores = leaky(K @ Q^T), batched over (h,n)    [512,128]@[512,128]^T
    gemm_k<<<dim3(8, 8, HH * NB), blk>>>(K, Q, nullptr, nullptr, S,
                                         MM, MM, DD,
                                         (int64_t)MM * DD, (int64_t)MM * DD, 0,
                                         (int64_t)MM * MM,
                                         F_TRANSB | F_LEAKY);
    // 5) softmax rows
    softmax_k<<<HH * NB * MM, blk>>>(S);
    // 6) att = leaky(alpha @ V)                          [512,512]@[512,128]
    gemm_k<<<dim3(2, 8, HH * NB), blk>>>(S, V, nullptr, nullptr, att,
                                         MM, DD, MM,
                                         (int64_t)MM * MM, (int64_t)MM * DD, 0,
                                         (int64_t)MM * DD, F_LEAKY);
    // 7) head concat
    reorder_k<<<1024, blk>>>((const float4*)att, (float4*)attc);
    // 8) f_v hidden: relu(attc @ fv_w1 + fv_b1)         [1024,1024]@[1024,128]
    gemm_k<<<dim3(2, 16, 1), blk>>>(attc, fv_w1, fv_b1, nullptr, t2,
                                    NM, DD, HH * DD, 0, 0, 0, 0, F_RELU | F_BIAS);
    // 9) x2 = t2 @ fv_w2 + fv_b2 + h                    [1024,128]@[128,128]
    gemm_k<<<dim3(2, 16, 1), blk>>>(t2, fv_w2, fv_b2, h, x2,
                                    NM, DD, DD, 0, 0, 0, 0, F_BIAS | F_ADD);
    // 10) A = x2 @ fe_w1[:128]; B = x2 @ fe_w1[128:]    batched z=2
    gemm_k<<<dim3(2, 16, 2), blk>>>(x2, fe_w1, nullptr, nullptr, ABuf,
                                    NM, DD, DD, 0, DD * DD, 0, (int64_t)NM * DD, 0);
    // 11) edge
    edge_k<<<dim3(16, 16, NB), blk>>>(ABuf, fe_b1, fe_w2, fe_b2, edge);
}

// round 2
// speedup vs baseline: 1.4622x; 1.4622x over previous
#include <cuda_runtime.h>
#include <math.h>
#include <stdint.h>

#define NB 2
#define MM 512
#define DD 128
#define HH 8
#define DIN 64
#define NM (NB*MM)   // 1024

// ---------------- scratch (device globals; no allocation allowed) ----------------
#define OFF_TMP  0                               // [NM, 2D]  f_node hidden
#define OFF_H    (OFF_TMP + NM*2*DD)             // [NM, D]   h
#define OFF_K    (OFF_H   + NM*DD)               // [H, NM, D]
#define OFF_Q    (OFF_K   + HH*NM*DD)
#define OFF_V    (OFF_Q   + HH*NM*DD)
#define OFF_S    (OFF_V   + HH*NM*DD)            // [H*N, M, M] scores/alpha
#define OFF_ATTC (OFF_S   + HH*NB*MM*MM)         // [NM, H*D] head-concat
#define OFF_T2   (OFF_ATTC+ HH*NM*DD)            // [NM, D]   f_v hidden
#define OFF_AB   (OFF_T2  + NM*DD)               // [2, NM, D] A/B for edges
#define SCRATCH_TOTAL (OFF_AB + 2*NM*DD)

__device__ float g_scratch[SCRATCH_TOTAL];

#define F_TRANSB 1
#define F_RELU   2
#define F_LEAKY  4
#define F_TE     8
#define F_BIAS   16
#define F_ADD    32

// ---------------- double-buffered fp32 GEMM body ---------------------------------
// 64x64 tile, 256 threads, 4x4 per thread, K-tile 16, 2-stage smem pipeline.
// A: [*,Kd] row-major. B: [Kd,Nc] (or [Nc,Kd] if TRANSB). C row stride = ldc.
template<int F>
__device__ __forceinline__ void gemm_body(
    const float* __restrict__ A, const float* __restrict__ B,
    const float* __restrict__ bias, const float* __restrict__ addsrc,
    float* __restrict__ C, int Kd, int Nc, int ldc)
{
    __shared__ float As[2][16][68];
    __shared__ float Bs[2][16][68];
    int tid = threadIdx.x;
    int tx = tid & 15, ty = tid >> 4;
    int m0 = blockIdx.y << 6, n0 = blockIdx.x << 6;
    float acc[4][4] = {};

    // A tile loader: 64 rows x 16 cols, one float4 per thread
    int ar = tid >> 2, ac = (tid & 3) << 2;
    const float* Ap = A + (int64_t)(m0 + ar) * Kd + ac;
    // B tile loader
    int br, bc;
    const float* Bp;
    if (F & F_TRANSB) { br = tid >> 2; bc = (tid & 3) << 2;
                        Bp = B + (int64_t)(n0 + br) * Kd + bc; }
    else              { br = tid >> 4; bc = (tid & 15) << 2;
                        Bp = B + (int64_t)br * Nc + n0 + bc; }

    const int nkt = Kd >> 4;

    // ---- prologue: load tile 0
    float4 a4 = *(const float4*)Ap;
    float4 b4;
    if (F & F_TRANSB) b4 = *(const float4*)Bp;
    else              b4 = *(const float4*)Bp;
    if (F & F_TE) {
        a4.x += sinf((float)(ac + 0) * (5.0f / 63.0f));
        a4.y += sinf((float)(ac + 1) * (5.0f / 63.0f));
        a4.z += sinf((float)(ac + 2) * (5.0f / 63.0f));
        a4.w += sinf((float)(ac + 3) * (5.0f / 63.0f));
    }
    As[0][ac + 0][ar] = a4.x; As[0][ac + 1][ar] = a4.y;
    As[0][ac + 2][ar] = a4.z; As[0][ac + 3][ar] = a4.w;
    if (F & F_TRANSB) {
        Bs[0][bc + 0][br] = b4.x; Bs[0][bc + 1][br] = b4.y;
        Bs[0][bc + 2][br] = b4.z; Bs[0][bc + 3][br] = b4.w;
    } else {
        *(float4*)&Bs[0][br][bc] = b4;
    }
    __syncthreads();

    int buf = 0;
    for (int kt = 0; kt < nkt; kt++) {
        float4 an, bn;
        bool more = (kt + 1 < nkt);
        if (more) {
            an = *(const float4*)(Ap + (kt + 1) * 16);
            if (F & F_TRANSB) bn = *(const float4*)(Bp + (kt + 1) * 16);
            else              bn = *(const float4*)(Bp + (int64_t)(kt + 1) * 16 * Nc);
            if (F & F_TE) {
                int kb = (kt + 1) * 16 + ac;
                an.x += sinf((float)(kb + 0) * (5.0f / 63.0f));
                an.y += sinf((float)(kb + 1) * (5.0f / 63.0f));
                an.z += sinf((float)(kb + 2) * (5.0f / 63.0f));
                an.w += sinf((float)(kb + 3) * (5.0f / 63.0f));
            }
        }
        #pragma unroll
        for (int kk = 0; kk < 16; kk++) {
            float4 av = *(const float4*)&As[buf][kk][ty << 2];
            float4 bv = *(const float4*)&Bs[buf][kk][tx << 2];
            float a[4] = {av.x, av.y, av.z, av.w};
            float b[4] = {bv.x, bv.y, bv.z, bv.w};
            #pragma unroll
            for (int i = 0; i < 4; i++)
                #pragma unroll
                for (int j = 0; j < 4; j++)
                    acc[i][j] = fmaf(a[i], b[j], acc[i][j]);
        }
        if (more) {
            int nb = buf ^ 1;
            As[nb][ac + 0][ar] = an.x; As[nb][ac + 1][ar] = an.y;
            As[nb][ac + 2][ar] = an.z; As[nb][ac + 3][ar] = an.w;
            if (F & F_TRANSB) {
                Bs[nb][bc + 0][br] = bn.x; Bs[nb][bc + 1][br] = bn.y;
                Bs[nb][bc + 2][br] = bn.z; Bs[nb][bc + 3][br] = bn.w;
            } else {
                *(float4*)&Bs[nb][br][bc] = bn;
            }
            __syncthreads();
            buf = nb;
        }
    }

    // ---- epilogue
    #pragma unroll
    for (int i = 0; i < 4; i++) {
        int row = m0 + (ty << 2) + i;
        int colb = n0 + (tx << 2);
        float o[4];
        #pragma unroll
        for (int j = 0; j < 4; j++) {
            float v = acc[i][j];
            if (F & F_BIAS)  v += bias[colb + j];
            if (F & F_RELU)  v = fmaxf(v, 0.0f);
            if (F & F_LEAKY) v = (v >= 0.0f) ? v : 0.2f * v;
            if (F & F_ADD)   v += addsrc[(int64_t)row * ldc + colb + j];
            o[j] = v;
        }
        *(float4*)&C[(int64_t)row * ldc + colb] = make_float4(o[0], o[1], o[2], o[3]);
    }
}

// ---------------- generic wrapper ------------------------------------------------
template<int F>
__global__ __launch_bounds__(256)
void gemm_k(const float* __restrict__ A, const float* __restrict__ B,
            const float* __restrict__ bias, const float* __restrict__ addsrc,
            float* __restrict__ C, int Kd, int Nc, int ldc,
            int64_t sA, int64_t sB, int64_t sBias,
            int zdiv, int64_t sC1, int64_t sC2)
{
    int z = blockIdx.z;
    const float* bz = (F & F_BIAS) ? bias + sBias * z : nullptr;
    gemm_body<F>(A + sA * z, B + sB * z, bz, addsrc,
                 C + (int64_t)(z / zdiv) * sC1 + (int64_t)(z % zdiv) * sC2,
                 Kd, Nc, ldc);
}

// ---------------- fused K/Q/V wrapper: z = which*8 + head -------------------------
__global__ __launch_bounds__(256)
void kqv_k(const float* __restrict__ h,
           const float* __restrict__ wk, const float* __restrict__ bk,
           const float* __restrict__ wq, const float* __restrict__ bq,
           const float* __restrict__ wv, const float* __restrict__ bv,
           float* __restrict__ out)
{
    int z = blockIdx.z;
    int which = z >> 3, head = z & 7;
    const float* W = (which == 0) ? wk : (which == 1) ? wq : wv;
    const float* Bi = (which == 0) ? bk : (which == 1) ? bq : bv;
    W  += (int64_t)head * DD * DD;
    Bi += (int64_t)head * DD;
    float* C = out + ((int64_t)which * HH + head) * NM * DD;
    gemm_body<F_BIAS>(h, W, Bi, nullptr, C, DD, DD, DD);
}

// ---------------- row softmax over 512 cols (one block per row) -------------------
__global__ __launch_bounds__(256)
void softmax_k(float* __restrict__ data)
{
    __shared__ float red[8];
    float* p = data + (int64_t)blockIdx.x * MM;
    int t = threadIdx.x;
    float v0 = p[t], v1 = p[t + 256];
    float m = fmaxf(v0, v1);
    #pragma unroll
    for (int o = 16; o; o >>= 1) m = fmaxf(m, __shfl_xor_sync(0xffffffffu, m, o));
    if ((t & 31) == 0) red[t >> 5] = m;
    __syncthreads();
    float bm = red[0];
    #pragma unroll
    for (int w = 1; w < 8; w++) bm = fmaxf(bm, red[w]);
    float e0 = __expf(v0 - bm), e1 = __expf(v1 - bm);
    float s = e0 + e1;
    #pragma unroll
    for (int o = 16; o; o >>= 1) s += __shfl_xor_sync(0xffffffffu, s, o);
    __syncthreads();
    if ((t & 31) == 0) red[t >> 5] = s;
    __syncthreads();
    float bs = red[0];
    #pragma unroll
    for (int w = 1; w < 8; w++) bs += red[w];
    float inv = 1.0f / bs;
    p[t] = e0 * inv;
    p[t + 256] = e1 * inv;
}

// ---------------- edge kernel: edge[n,i,j] = (sum_d relu(A_i+B_j+b1)*w2 + b2)/M ---
__global__ __launch_bounds__(256)
void edge_k(const float* __restrict__ AB, const float* __restrict__ b1,
            const float* __restrict__ w2, const float* __restrict__ b2,
            float* __restrict__ out)
{
    __shared__ float Ast[DD][36];
    __shared__ float Bst[DD][36];
    __shared__ float w2s[DD];
    int n  = blockIdx.z;
    int i0 = blockIdx.y << 5, j0 = blockIdx.x << 5;
    const float* Ab = AB + ((int64_t)n * MM + i0) * DD;
    const float* Bb = AB + (int64_t)NM * DD + ((int64_t)n * MM + j0) * DD;
    int t = threadIdx.x;
    if (t < DD) w2s[t] = w2[t];
    #pragma unroll
    for (int c = 0; c < 4; c++) {
        int idx = t + (c << 8);
        int r  = idx >> 5;
        int d4 = (idx & 31) << 2;
        float4 a = *(const float4*)(Ab + r * DD + d4);
        Ast[d4 + 0][r] = a.x; Ast[d4 + 1][r] = a.y;
        Ast[d4 + 2][r] = a.z; Ast[d4 + 3][r] = a.w;
        float4 bvl = *(const float4*)(Bb + r * DD + d4);
        float4 bb  = *(const float4*)(b1 + d4);
        Bst[d4 + 0][r] = bvl.x + bb.x; Bst[d4 + 1][r] = bvl.y + bb.y;
        Bst[d4 + 2][r] = bvl.z + bb.z; Bst[d4 + 3][r] = bvl.w + bb.w;
    }
    __syncthreads();
    int tx = t & 15, ty = t >> 4;
    float a00 = 0.f, a01 = 0.f, a10 = 0.f, a11 = 0.f;
    #pragma unroll 8
    for (int d = 0; d < DD; d++) {
        float2 av = *(const float2*)&Ast[d][ty << 1];
        float2 bv = *(const float2*)&Bst[d][tx << 1];
        float w = w2s[d];
        a00 = fmaf(fmaxf(av.x + bv.x, 0.f), w, a00);
        a01 = fmaf(fmaxf(av.x + bv.y, 0.f), w, a01);
        a10 = fmaf(fmaxf(av.y + bv.x, 0.f), w, a10);
        a11 = fmaf(fmaxf(av.y + bv.y, 0.f), w, a11);
    }
    float bb = b2[0];
    const float sc = 1.0f / (float)MM;
    int i = i0 + (ty << 1), j = j0 + (tx << 1);
    float* o = out + ((int64_t)n * MM + i) * MM + j;
    o[0]      = (a00 + bb) * sc;
    o[1]      = (a01 + bb) * sc;
    o[MM]     = (a10 + bb) * sc;
    o[MM + 1] = (a11 + bb) * sc;
}

// ---------------- host launcher ---------------------------------------------------
extern "C" void kernel_launch(void* const* d_in, const int* in_sizes, int n_in,
                              void* d_out, int out_size)
{
    const float* x     = (const float*)d_in[0];
    const float* fn_w1 = (const float*)d_in[1];
    const float* fn_b1 = (const float*)d_in[2];
    const float* fn_w2 = (const float*)d_in[3];
    const float* fn_b2 = (const float*)d_in[4];
    const float* wk    = (const float*)d_in[5];
    const float* bk    = (const float*)d_in[6];
    const float* wq    = (const float*)d_in[7];
    const float* bq    = (const float*)d_in[8];
    const float* wv    = (const float*)d_in[9];
    const float* bv    = (const float*)d_in[10];
    const float* fv_w1 = (const float*)d_in[11];
    const float* fv_b1 = (const float*)d_in[12];
    const float* fv_w2 = (const float*)d_in[13];
    const float* fv_b2 = (const float*)d_in[14];
    const float* fe_w1 = (const float*)d_in[15];
    const float* fe_b1 = (const float*)d_in[16];
    const float* fe_w2 = (const float*)d_in[17];
    const float* fe_b2 = (const float*)d_in[18];

    float* scratch = nullptr;
    cudaGetSymbolAddress((void**)&scratch, g_scratch);
    float* tmp  = scratch + OFF_TMP;
    float* h    = scratch + OFF_H;
    float* K    = scratch + OFF_K;
    float* V    = scratch + OFF_V;
    float* S    = scratch + OFF_S;
    float* attc = scratch + OFF_ATTC;
    float* t2   = scratch + OFF_T2;
    float* ABuf = scratch + OFF_AB;

    float* x2   = (float*)d_out;
    float* edge = (float*)d_out + NM * DD;

    dim3 blk(256);

    // 1) f_node hidden: relu((x+te) @ fn_w1 + fn_b1)  [1024,64]@[64,256]
    gemm_k<F_TE | F_RELU | F_BIAS><<<dim3(4, 16, 1), blk>>>(
        x, fn_w1, fn_b1, nullptr, tmp, DIN, 2 * DD, 2 * DD, 0, 0, 0, 1, 0, 0);
    // 2) h = tmp @ fn_w2 + fn_b2                      [1024,256]@[256,128]
    gemm_k<F_BIAS><<<dim3(2, 16, 1), blk>>>(
        tmp, fn_w2, fn_b2, nullptr, h, 2 * DD, DD, DD, 0, 0, 0, 1, 0, 0);
    // 3) fused K/Q/V over 24 (which,head) pairs
    kqv_k<<<dim3(2, 16, 24), blk>>>(h, wk, bk, wq, bq, wv, bv, K);
    // 4) scores = leaky(K @ Q^T), batched over (h,n)  z = h*2+n
    gemm_k<F_TRANSB | F_LEAKY><<<dim3(8, 8, HH * NB), blk>>>(
        K, K + HH * NM * DD /*Q*/, nullptr, nullptr, S,
        DD, MM, MM, (int64_t)MM * DD, (int64_t)MM * DD, 0,
        1, (int64_t)MM * MM, 0);
    // 5) softmax rows
    softmax_k<<<HH * NB * MM, blk>>>(S);
    // 6) att = leaky(alpha @ V), write straight into concat layout [NM, H*D]
    gemm_k<F_LEAKY><<<dim3(2, 8, HH * NB), blk>>>(
        S, V, nullptr, nullptr, attc,
        MM, DD, HH * DD, (int64_t)MM * MM, (int64_t)MM * DD, 0,
        2, (int64_t)DD, (int64_t)MM * HH * DD);
    // 7) f_v hidden: relu(attc @ fv_w1 + fv_b1)       [1024,1024]@[1024,128]
    gemm_k<F_RELU | F_BIAS><<<dim3(2, 16, 1), blk>>>(
        attc, fv_w1, fv_b1, nullptr, t2, HH * DD, DD, DD, 0, 0, 0, 1, 0, 0);
    // 8) x2 = t2 @ fv_w2 + fv_b2 + h                  [1024,128]@[128,128]
    gemm_k<F_BIAS | F_ADD><<<dim3(2, 16, 1), blk>>>(
        t2, fv_w2, fv_b2, h, x2, DD, DD, DD, 0, 0, 0, 1, 0, 0);
    // 9) A = x2 @ fe_w1[:128]; B = x2 @ fe_w1[128:]   batched z=2
    gemm_k<0><<<dim3(2, 16, 2), blk>>>(
        x2, fe_w1, nullptr, nullptr, ABuf, DD, DD, DD,
        0, (int64_t)DD * DD, 0, 1, (int64_t)NM * DD, 0);
    // 10) edge
    edge_k<<<dim3(16, 16, NB), blk>>>(ABuf, fe_b1, fe_w2, fe_b2, edge);
}

// round 3
// speedup vs baseline: 1.5263x; 1.0438x over previous
#include <cuda_runtime.h>
#include <math.h>
#include <stdint.h>

#define NB 2
#define MM 512
#define DD 128
#define HH 8
#define DIN 64
#define NM (NB*MM)   // 1024

typedef unsigned long long u64;

// ---------------- packed f32x2 helpers --------------------------------------------
__device__ __forceinline__ u64 pk2(float lo, float hi) {
    u64 r; asm("mov.b64 %0, {%1,%2};" : "=l"(r) : "f"(lo), "f"(hi)); return r;
}
__device__ __forceinline__ void fma2(u64& d, u64 a, u64 b) {
    asm("fma.rn.f32x2 %0, %1, %2, %0;" : "+l"(d) : "l"(a), "l"(b));
}
__device__ __forceinline__ float2 up2(u64 v) {
    float lo, hi; asm("mov.b64 {%0,%1}, %2;" : "=f"(lo), "=f"(hi) : "l"(v));
    return make_float2(lo, hi);
}

// ---------------- scratch ---------------------------------------------------------
#define OFF_TMP  0
#define OFF_H    (OFF_TMP + NM*2*DD)
#define OFF_K    (OFF_H   + NM*DD)
#define OFF_Q    (OFF_K   + HH*NM*DD)
#define OFF_V    (OFF_Q   + HH*NM*DD)
#define OFF_S    (OFF_V   + HH*NM*DD)            // [H*N, M, M]; also reused for K-split partials
#define OFF_ATTC (OFF_S   + HH*NB*MM*MM)         // [NM, H*D]
#define OFF_T2   (OFF_ATTC+ HH*NM*DD)
#define OFF_AB   (OFF_T2  + NM*DD)
#define SCRATCH_TOTAL (OFF_AB + 2*NM*DD)

__device__ float g_scratch[SCRATCH_TOTAL];

#define F_TRANSB 1
#define F_RELU   2
#define F_LEAKY  4
#define F_TE     8
#define F_BIAS   16
#define F_ADD    32

// ---------------- FFMA2 GEMM body -------------------------------------------------
// tile 64(M) x 128(N), 128 threads, thread tile 8x8 (rows {4ty..+3, 32+4ty..+3},
// cols {4tx..+3, 64+4tx..+3}), K-tile 16, double buffered, packed f32x2 math.
template<int F>
__device__ __forceinline__ void gemm_body(
    const float* __restrict__ A, const float* __restrict__ B,
    const float* __restrict__ bias, const float* __restrict__ addsrc,
    float* __restrict__ C, int Kd, int Nc, int ldc, int ktb, int kte)
{
    __shared__ float As[2][16][64];
    __shared__ float Bs[2][16][128];
    int tid = threadIdx.x;
    int tx = tid & 15, ty = tid >> 4;
    int m0 = blockIdx.y << 6, n0 = blockIdx.x << 7;

    // A loader: 64x16 tile, thread = (row=tid>>1, colchunk=(tid&1)*8)
    int ar = tid >> 1, ac = (tid & 1) << 3;
    const float* Ap = A + (int64_t)(m0 + ar) * Kd + ac;
    // B loader
    int bk = tid >> 3, bc = (tid & 7) << 4;                 // non-trans
    const float* Bp = (F & F_TRANSB)
        ? B + (int64_t)(n0 + tid) * Kd                      // trans: one n-row/thread
        : B + (int64_t)bk * Nc + n0 + bc;

    u64 acc[8][4];
    #pragma unroll
    for (int i = 0; i < 8; i++)
        #pragma unroll
        for (int p = 0; p < 4; p++) acc[i][p] = 0ull;

    float4 la0, la1, lb[4];

    auto loadG = [&](int kt) {
        la0 = *(const float4*)(Ap + kt * 16);
        la1 = *(const float4*)(Ap + kt * 16 + 4);
        if (F & F_TE) {
            int kb = kt * 16 + ac;
            la0.x += sinf((float)(kb + 0) * (5.0f / 63.0f));
            la0.y += sinf((float)(kb + 1) * (5.0f / 63.0f));
            la0.z += sinf((float)(kb + 2) * (5.0f / 63.0f));
            la0.w += sinf((float)(kb + 3) * (5.0f / 63.0f));
            la1.x += sinf((float)(kb + 4) * (5.0f / 63.0f));
            la1.y += sinf((float)(kb + 5) * (5.0f / 63.0f));
            la1.z += sinf((float)(kb + 6) * (5.0f / 63.0f));
            la1.w += sinf((float)(kb + 7) * (5.0f / 63.0f));
        }
        if (F & F_TRANSB) {
            #pragma unroll
            for (int u = 0; u < 4; u++)
                lb[u] = *(const float4*)(Bp + kt * 16 + 4 * u);
        } else {
            #pragma unroll
            for (int u = 0; u < 4; u++)
                lb[u] = *(const float4*)(Bp + (int64_t)(kt * 16) * Nc + 4 * u);
        }
    };
    auto storeS = [&](int bf) {
        As[bf][ac + 0][ar] = la0.x; As[bf][ac + 1][ar] = la0.y;
        As[bf][ac + 2][ar] = la0.z; As[bf][ac + 3][ar] = la0.w;
        As[bf][ac + 4][ar] = la1.x; As[bf][ac + 5][ar] = la1.y;
        As[bf][ac + 6][ar] = la1.z; As[bf][ac + 7][ar] = la1.w;
        if (F & F_TRANSB) {
            #pragma unroll
            for (int u = 0; u < 4; u++) {
                Bs[bf][4 * u + 0][tid] = lb[u].x; Bs[bf][4 * u + 1][tid] = lb[u].y;
                Bs[bf][4 * u + 2][tid] = lb[u].z; Bs[bf][4 * u + 3][tid] = lb[u].w;
            }
        } else {
            #pragma unroll
            for (int u = 0; u < 4; u++)
                *(float4*)&Bs[bf][bk][bc + 4 * u] = lb[u];
        }
    };

    loadG(ktb); storeS(0); __syncthreads();
    int buf = 0;
    for (int kt = ktb; kt < kte; kt++) {
        bool more = (kt + 1 < kte);
        if (more) loadG(kt + 1);
        #pragma unroll
        for (int kk = 0; kk < 16; kk++) {
            float4 alo = *(const float4*)&As[buf][kk][ty << 2];
            float4 ahi = *(const float4*)&As[buf][kk][32 + (ty << 2)];
            ulonglong2 bb0 = *(const ulonglong2*)&Bs[buf][kk][tx << 2];
            ulonglong2 bb1 = *(const ulonglong2*)&Bs[buf][kk][64 + (tx << 2)];
            u64 ad[8];
            ad[0] = pk2(alo.x, alo.x); ad[1] = pk2(alo.y, alo.y);
            ad[2] = pk2(alo.z, alo.z); ad[3] = pk2(alo.w, alo.w);
            ad[4] = pk2(ahi.x, ahi.x); ad[5] = pk2(ahi.y, ahi.y);
            ad[6] = pk2(ahi.z, ahi.z); ad[7] = pk2(ahi.w, ahi.w);
            #pragma unroll
            for (int i = 0; i < 8; i++) {
                fma2(acc[i][0], ad[i], bb0.x);
                fma2(acc[i][1], ad[i], bb0.y);
                fma2(acc[i][2], ad[i], bb1.x);
                fma2(acc[i][3], ad[i], bb1.y);
            }
        }
        if (more) { storeS(buf ^ 1); __syncthreads(); buf ^= 1; }
    }

    // ---- epilogue: two float4 chunks per row (cols 4tx.. and 64+4tx..)
    #pragma unroll
    for (int i = 0; i < 8; i++) {
        int row = m0 + ((i < 4) ? ((ty << 2) + i) : (32 + (ty << 2) + i - 4));
        float2 c0 = up2(acc[i][0]), c1 = up2(acc[i][1]);
        float2 c2 = up2(acc[i][2]), c3 = up2(acc[i][3]);
        float o[8] = {c0.x, c0.y, c1.x, c1.y, c2.x, c2.y, c3.x, c3.y};
        #pragma unroll
        for (int j = 0; j < 8; j++) {
            int col = n0 + ((j < 4) ? ((tx << 2) + j) : (64 + (tx << 2) + j - 4));
            float v = o[j];
            if (F & F_BIAS)  v += bias[col];
            if (F & F_RELU)  v = fmaxf(v, 0.0f);
            if (F & F_LEAKY) v = (v >= 0.0f) ? v : 0.2f * v;
            if (F & F_ADD)   v += addsrc[(int64_t)row * ldc + col];
            o[j] = v;
        }
        *(float4*)&C[(int64_t)row * ldc + n0 + (tx << 2)]      = make_float4(o[0], o[1], o[2], o[3]);
        *(float4*)&C[(int64_t)row * ldc + n0 + 64 + (tx << 2)] = make_float4(o[4], o[5], o[6], o[7]);
    }
}

// ---------------- generic wrapper (with optional K-split) --------------------------
template<int F, int NKS>
__global__ __launch_bounds__(128, 4)
void gemm_k(const float* __restrict__ A, const float* __restrict__ B,
            const float* __restrict__ bias, const float* __restrict__ addsrc,
            float* __restrict__ C, int Kd, int Nc, int ldc,
            int64_t sA, int64_t sB, int64_t sBias,
            int zdiv, int64_t sC1, int64_t sC2, int64_t sPart)
{
    int zz = blockIdx.z;
    int z = zz / NKS, ks = zz % NKS;
    int ktn = Kd >> 4;
    int ktb = ks * (ktn / NKS), kte = ktb + ktn / NKS;
    const float* bz = (F & F_BIAS) ? bias + sBias * z : nullptr;
    float* Cz = C + (int64_t)(z / zdiv) * sC1 + (int64_t)(z % zdiv) * sC2
                  + (int64_t)ks * sPart;
    gemm_body<F>(A + sA * z, B + sB * z, bz, addsrc, Cz, Kd, Nc, ldc, ktb, kte);
}

// ---------------- fused K/Q/V wrapper: z = which*8 + head --------------------------
__global__ __launch_bounds__(128, 4)
void kqv_k(const float* __restrict__ h,
           const float* __restrict__ wk, const float* __restrict__ bk,
           const float* __restrict__ wq, const float* __restrict__ bq,
           const float* __restrict__ wv, const float* __restrict__ bv,
           float* __restrict__ out)
{
    int z = blockIdx.z;
    int which = z >> 3, head = z & 7;
    const float* W  = (which == 0) ? wk : (which == 1) ? wq : wv;
    const float* Bi = (which == 0) ? bk : (which == 1) ? bq : bv;
    W  += (int64_t)head * DD * DD;
    Bi += (int64_t)head * DD;
    float* C = out + ((int64_t)which * HH + head) * NM * DD;
    gemm_body<F_BIAS>(h, W, Bi, nullptr, C, DD, DD, DD, 0, DD / 16);
}

// ---------------- K-split reduce: C = act(sum_ks P + bias) -------------------------
template<int F, int NKS>
__global__ __launch_bounds__(256)
void reduce_k(const float4* __restrict__ P, const float* __restrict__ bias,
              float4* __restrict__ C, int totalf4, int ncf4)
{
    int idx = blockIdx.x * 256 + threadIdx.x;
    if (idx >= totalf4) return;
    float4 s = P[idx];
    #pragma unroll
    for (int k = 1; k < NKS; k++) {
        float4 t = P[idx + (int64_t)k * totalf4];
        s.x += t.x; s.y += t.y; s.z += t.z; s.w += t.w;
    }
    if (F & F_BIAS) {
        float4 b = ((const float4*)bias)[idx % ncf4];
        s.x += b.x; s.y += b.y; s.z += b.z; s.w += b.w;
    }
    if (F & F_RELU) {
        s.x = fmaxf(s.x, 0.f); s.y = fmaxf(s.y, 0.f);
        s.z = fmaxf(s.z, 0.f); s.w = fmaxf(s.w, 0.f);
    }
    C[idx] = s;
}

// ---------------- row softmax over 512 cols ---------------------------------------
__global__ __launch_bounds__(256)
void softmax_k(float* __restrict__ data)
{
    __shared__ float red[8];
    float* p = data + (int64_t)blockIdx.x * MM;
    int t = threadIdx.x;
    float v0 = p[t], v1 = p[t + 256];
    float m = fmaxf(v0, v1);
    #pragma unroll
    for (int o = 16; o; o >>= 1) m = fmaxf(m, __shfl_xor_sync(0xffffffffu, m, o));
    if ((t & 31) == 0) red[t >> 5] = m;
    __syncthreads();
    float bm = red[0];
    #pragma unroll
    for (int w = 1; w < 8; w++) bm = fmaxf(bm, red[w]);
    float e0 = __expf(v0 - bm), e1 = __expf(v1 - bm);
    float s = e0 + e1;
    #pragma unroll
    for (int o = 16; o; o >>= 1) s += __shfl_xor_sync(0xffffffffu, s, o);
    __syncthreads();
    if ((t & 31) == 0) red[t >> 5] = s;
    __syncthreads();
    float bs = red[0];
    #pragma unroll
    for (int w = 1; w < 8; w++) bs += red[w];
    float inv = 1.0f / bs;
    p[t] = e0 * inv;
    p[t + 256] = e1 * inv;
}

// ---------------- edge kernel ------------------------------------------------------
__global__ __launch_bounds__(256)
void edge_k(const float* __restrict__ AB, const float* __restrict__ b1,
            const float* __restrict__ w2, const float* __restrict__ b2,
            float* __restrict__ out)
{
    __shared__ float Ast[DD][36];
    __shared__ float Bst[DD][36];
    __shared__ float w2s[DD];
    int n  = blockIdx.z;
    int i0 = blockIdx.y << 5, j0 = blockIdx.x << 5;
    const float* Ab = AB + ((int64_t)n * MM + i0) * DD;
    const float* Bb = AB + (int64_t)NM * DD + ((int64_t)n * MM + j0) * DD;
    int t = threadIdx.x;
    if (t < DD) w2s[t] = w2[t];
    #pragma unroll
    for (int c = 0; c < 4; c++) {
        int idx = t + (c << 8);
        int r  = idx >> 5;
        int d4 = (idx & 31) << 2;
        float4 a = *(const float4*)(Ab + r * DD + d4);
        Ast[d4 + 0][r] = a.x; Ast[d4 + 1][r] = a.y;
        Ast[d4 + 2][r] = a.z; Ast[d4 + 3][r] = a.w;
        float4 bvl = *(const float4*)(Bb + r * DD + d4);
        float4 bb  = *(const float4*)(b1 + d4);
        Bst[d4 + 0][r] = bvl.x + bb.x; Bst[d4 + 1][r] = bvl.y + bb.y;
        Bst[d4 + 2][r] = bvl.z + bb.z; Bst[d4 + 3][r] = bvl.w + bb.w;
    }
    __syncthreads();
    int tx = t & 15, ty = t >> 4;
    float a00 = 0.f, a01 = 0.f, a10 = 0.f, a11 = 0.f;
    #pragma unroll 8
    for (int d = 0; d < DD; d++) {
        float2 av = *(const float2*)&Ast[d][ty << 1];
        float2 bv = *(const float2*)&Bst[d][tx << 1];
        float w = w2s[d];
        a00 = fmaf(fmaxf(av.x + bv.x, 0.f), w, a00);
        a01 = fmaf(fmaxf(av.x + bv.y, 0.f), w, a01);
        a10 = fmaf(fmaxf(av.y + bv.x, 0.f), w, a10);
        a11 = fmaf(fmaxf(av.y + bv.y, 0.f), w, a11);
    }
    float bb = b2[0];
    const float sc = 1.0f / (float)MM;
    int i = i0 + (ty << 1), j = j0 + (tx << 1);
    float* o = out + ((int64_t)n * MM + i) * MM + j;
    o[0]      = (a00 + bb) * sc;
    o[1]      = (a01 + bb) * sc;
    o[MM]     = (a10 + bb) * sc;
    o[MM + 1] = (a11 + bb) * sc;
}

// ---------------- host launcher ----------------------------------------------------
extern "C" void kernel_launch(void* const* d_in, const int* in_sizes, int n_in,
                              void* d_out, int out_size)
{
    const float* x     = (const float*)d_in[0];
    const float* fn_w1 = (const float*)d_in[1];
    const float* fn_b1 = (const float*)d_in[2];
    const float* fn_w2 = (const float*)d_in[3];
    const float* fn_b2 = (const float*)d_in[4];
    const float* wk    = (const float*)d_in[5];
    const float* bk    = (const float*)d_in[6];
    const float* wq    = (const float*)d_in[7];
    const float* bq    = (const float*)d_in[8];
    const float* wv    = (const float*)d_in[9];
    const float* bv    = (const float*)d_in[10];
    const float* fv_w1 = (const float*)d_in[11];
    const float* fv_b1 = (const float*)d_in[12];
    const float* fv_w2 = (const float*)d_in[13];
    const float* fv_b2 = (const float*)d_in[14];
    const float* fe_w1 = (const float*)d_in[15];
    const float* fe_b1 = (const float*)d_in[16];
    const float* fe_w2 = (const float*)d_in[17];
    const float* fe_b2 = (const float*)d_in[18];

    float* scratch = nullptr;
    cudaGetSymbolAddress((void**)&scratch, g_scratch);
    float* tmp  = scratch + OFF_TMP;
    float* h    = scratch + OFF_H;
    float* K    = scratch + OFF_K;
    float* V    = scratch + OFF_V;
    float* S    = scratch + OFF_S;
    float* P    = scratch + OFF_S;       // K-split partials (S region is dead then)
    float* attc = scratch + OFF_ATTC;
    float* t2   = scratch + OFF_T2;
    float* ABuf = scratch + OFF_AB;

    float* x2   = (float*)d_out;
    float* edge = (float*)d_out + NM * DD;

    dim3 gb(128);
    const int MN4 = NM * DD / 4;   // 32768 float4
    const int NC4 = DD / 4;        // 32

    // 1) f_node hidden: relu((x+te) @ fn_w1 + fn_b1)  [1024,64]@[64,256]
    gemm_k<F_TE | F_RELU | F_BIAS, 1><<<dim3(2, 16, 1), gb>>>(
        x, fn_w1, fn_b1, nullptr, tmp, DIN, 2 * DD, 2 * DD, 0, 0, 0, 1, 0, 0, 0);
    // 2) h = tmp @ fn_w2 + fn_b2  — K-split 4, then reduce
    gemm_k<0, 4><<<dim3(1, 16, 4), gb>>>(
        tmp, fn_w2, nullptr, nullptr, P, 2 * DD, DD, DD, 0, 0, 0, 1, 0, 0,
        (int64_t)NM * DD);
    reduce_k<F_BIAS, 4><<<128, 256>>>((const float4*)P, fn_b2, (float4*)h, MN4, NC4);
    // 3) fused K/Q/V over 24 (which,head) pairs
    kqv_k<<<dim3(1, 16, 24), gb>>>(h, wk, bk, wq, bq, wv, bv, K);
    // 4) scores = leaky(K @ Q^T), z = h*2+n
    gemm_k<F_TRANSB | F_LEAKY, 1><<<dim3(4, 8, HH * NB), gb>>>(
        K, K + HH * NM * DD /*Q*/, nullptr, nullptr, S,
        DD, MM, MM, (int64_t)MM * DD, (int64_t)MM * DD, 0,
        1, (int64_t)MM * MM, 0, 0);
    // 5) softmax rows
    softmax_k<<<HH * NB * MM, 256>>>(S);
    // 6) att = leaky(alpha @ V), written into concat layout [NM, H*D]
    gemm_k<F_LEAKY, 1><<<dim3(1, 8, HH * NB), gb>>>(
        S, V, nullptr, nullptr, attc,
        MM, DD, HH * DD, (int64_t)MM * MM, (int64_t)MM * DD, 0,
        2, (int64_t)DD, (int64_t)MM * HH * DD, 0);
    // 7) f_v hidden — K-split 8, then reduce (bias+relu)
    gemm_k<0, 8><<<dim3(1, 16, 8), gb>>>(
        attc, fv_w1, nullptr, nullptr, P, HH * DD, DD, DD, 0, 0, 0, 1, 0, 0,
        (int64_t)NM * DD);
    reduce_k<F_BIAS | F_RELU, 8><<<128, 256>>>((const float4*)P, fv_b1, (float4*)t2,
                                               MN4, NC4);
    // 8) x2 = t2 @ fv_w2 + fv_b2 + h
    gemm_k<F_BIAS | F_ADD, 1><<<dim3(1, 16, 1), gb>>>(
        t2, fv_w2, fv_b2, h, x2, DD, DD, DD, 0, 0, 0, 1, 0, 0, 0);
    // 9) A = x2 @ fe_w1[:128]; B = x2 @ fe_w1[128:]
    gemm_k<0, 1><<<dim3(1, 16, 2), gb>>>(
        x2, fe_w1, nullptr, nullptr, ABuf, DD, DD, DD,
        0, (int64_t)DD * DD, 0, 1, (int64_t)NM * DD, 0, 0);
    // 10) edge
    edge_k<<<dim3(16, 16, NB), 256>>>(ABuf, fe_b1, fe_w2, fe_b2, edge);
}